// round 13
// baseline (speedup 1.0000x reference)
#include <cuda_runtime.h>
#include <cuda_bf16.h>
#include <math.h>

#define D      256
#define BATCH  512
#define CCH    10
#define NBP    10
#define NIV    11
#define FC1N   (BATCH * D)   // 131072

// ---- persistent device scratch ----
__device__ float  g_rs[BATCH * D];
__device__ float  g_cs[BATCH * D];
__device__ float  g_bp[NBP];
__device__ float4 g_tab4[NIV * 5];   // packed (a,b) pairs: idx*5 + q
__device__ float4 g_part4[BATCH];
__device__ float  g_b2c0[2];         // b2, relu(b2)
__device__ float  g_pad_sink;

// 16 per-warp work lists of (jbase, o0, o1, addConstFlag); jbase<0 = end.
// Block = output rows [o0,o1] of the 30-wide column strip at jbase.
// Iters/list: 86,88,88,79,78,77,69,68,67,85,87,72,70,91,88,80 (avg ~79).
__constant__ int4 c_blk[16][2] = {
    { {  0,   0,  83, 0}, { -1, 0, 0, 0} },
    { {  0,  84, 169, 0}, { -1, 0, 0, 0} },
    { {  0, 170, 255, 0}, { -1, 0, 0, 0} },
    { { 30,  28, 104, 1}, { -1, 0, 0, 0} },
    { { 30, 105, 180, 0}, { -1, 0, 0, 0} },
    { { 30, 181, 255, 0}, { -1, 0, 0, 0} },
    { { 60,  58, 124, 1}, { -1, 0, 0, 0} },
    { { 60, 125, 190, 0}, { -1, 0, 0, 0} },
    { { 60, 191, 255, 0}, { -1, 0, 0, 0} },
    { { 90,  88, 170, 1}, { -1, 0, 0, 0} },
    { { 90, 171, 255, 0}, { -1, 0, 0, 0} },
    { {120, 118, 187, 1}, { -1, 0, 0, 0} },
    { {120, 188, 255, 0}, { -1, 0, 0, 0} },
    { {150, 148, 188, 1}, {210, 208, 255, 1} },
    { {150, 189, 255, 0}, {240, 238, 255, 1} },
    { {180, 178, 255, 1}, { -1, 0, 0, 0} },
};

// ------------------------------------------------------------------
__global__ void setup_kernel(const float* __restrict__ w1, const float* __restrict__ b1,
                             const float* __restrict__ w2, const float* __restrict__ b2) {
    __shared__ float se[NIV];
    if (threadIdx.x == 0) {
        float bp[NBP];
        for (int c = 0; c < CCH; ++c) {
            float w = w1[c], bb = b1[c];
            bp[c] = (fabsf(w) < 1e-35f) ? ((bb > 0.f) ? 3e37f : -3e37f) : (-bb / w);
        }
        for (int a = 1; a < NBP; ++a) {
            float key = bp[a]; int q = a - 1;
            while (q >= 0 && bp[q] > key) { bp[q + 1] = bp[q]; --q; }
            bp[q + 1] = key;
        }
        for (int m = 0; m < NBP; ++m) g_bp[m] = bp[m];
        se[0]   = bp[0]       - fmaxf(1.f, 0.5f * fabsf(bp[0]));
        se[NBP] = bp[NBP - 1] + fmaxf(1.f, 0.5f * fabsf(bp[NBP - 1]));
        for (int m = 1; m < NBP; ++m) se[m] = 0.5f * bp[m - 1] + 0.5f * bp[m];
        g_b2c0[0] = b2[0];
        g_b2c0[1] = fmaxf(b2[0], 0.f);
    }
    __syncthreads();
    int m = threadIdx.x;
    if (m < NIV) {
        float e = se[m];
        float vals[20];
        for (int pos = 0; pos < 9; ++pos) {
            float a = 0.f, bb = 0.f;
            for (int c = 0; c < CCH; ++c) {
                float wv = w1[c], b1c = b1[c];
                if (wv * e + b1c > 0.f) {
                    float ww2 = w2[c * 9 + pos];
                    a  += wv  * ww2;
                    bb += b1c * ww2;
                }
            }
            vals[2 * pos]     = a;
            vals[2 * pos + 1] = bb;
        }
        vals[18] = 0.f; vals[19] = 0.f;
        for (int q = 0; q < 5; ++q)
            g_tab4[m * 5 + q] = make_float4(vals[4 * q], vals[4 * q + 1],
                                            vals[4 * q + 2], vals[4 * q + 3]);
    }
}

// ------------------------------------------------------------------
__global__ void __launch_bounds__(256) rowcol_kernel(const float* __restrict__ x) {
    int b    = blockIdx.x;
    int tid  = threadIdx.x;
    int g    = tid >> 6;
    int t    = tid & 63;
    int lane = tid & 31, warp = tid >> 5;
    __shared__ float sPart[D][2];
    __shared__ float sCs[4][D];
    const float4* xb = reinterpret_cast<const float4*>(x + (size_t)b * D * D);

    float c0 = 0.f, c1 = 0.f, c2 = 0.f, c3 = 0.f;
#pragma unroll 4
    for (int itr = 0; itr < 64; ++itr) {
        int i = g + (itr << 2);
        float4 v = xb[i * 64 + t];
        c0 += v.x; c1 += v.y; c2 += v.z; c3 += v.w;
        float s = (v.x + v.y) + (v.z + v.w);
        s += __shfl_down_sync(0xffffffffu, s, 16);
        s += __shfl_down_sync(0xffffffffu, s, 8);
        s += __shfl_down_sync(0xffffffffu, s, 4);
        s += __shfl_down_sync(0xffffffffu, s, 2);
        s += __shfl_down_sync(0xffffffffu, s, 1);
        if (lane == 0) sPart[i][warp & 1] = s;
    }
    sCs[g][t * 4 + 0] = c0;
    sCs[g][t * 4 + 1] = c1;
    sCs[g][t * 4 + 2] = c2;
    sCs[g][t * 4 + 3] = c3;
    __syncthreads();
    int j = tid;
    g_rs[b * D + j] = sPart[j][0] + sPart[j][1];
    g_cs[b * D + j] = sCs[0][j] + sCs[1][j] + sCs[2][j] + sCs[3][j];
}

// ------------------------------------------------------------------
__global__ void pad_kernel() {
    if (threadIdx.x == 0 && blockIdx.x == 0) g_pad_sink = 1.0f;
}

// ------------------------------------------------------------------
// conv: 512 threads / 16 warps per CTA, 16 balanced work lists.
// Steady loop unconditional (invalid halo lanes use zeroed table region).
// ------------------------------------------------------------------
__global__ void __launch_bounds__(512, 2) conv_kernel(const float* __restrict__ fc1_w) {
    int b    = blockIdx.x;
    int tid  = threadIdx.x;
    int w    = tid >> 5, lane = tid & 31;

    __shared__ __align__(16) float s_rs[D + 8];
    __shared__ float  s_cs[D];
    __shared__ float4 s_fw4[D];
    __shared__ float4 s_tab4[110];    // [0,55) real table, [55,110) zeros
    __shared__ float4 s_chunk[9];
    __shared__ float4 s_red[16];

    if (tid < 256) {
        s_rs[tid] = g_rs[b * D + tid];
        s_cs[tid] = g_cs[b * D + tid];
        float4 f;
        f.x = fc1_w[0 * FC1N + b * D + tid];
        f.y = fc1_w[1 * FC1N + b * D + tid];
        f.z = fc1_w[2 * FC1N + b * D + tid];
        f.w = fc1_w[3 * FC1N + b * D + tid];
        s_fw4[tid] = f;
    } else {
        int r = tid - 256;
        if (r < 8) s_rs[D + r] = 0.f;
        if (r < 55)        s_tab4[r] = g_tab4[r];
        else if (r < 110)  s_tab4[r] = make_float4(0.f, 0.f, 0.f, 0.f);
    }

    float bp[NBP];
#pragma unroll
    for (int m = 0; m < NBP; ++m) bp[m] = g_bp[m];
    float b2v = g_b2c0[0], cst = g_b2c0[1];
    __syncthreads();

    // 30-wide chunk sums of fw (warp c -> chunk c, c<9), for constant region
    if (w < 9) {
        int i = w * 30 + lane;
        float4 f = make_float4(0.f, 0.f, 0.f, 0.f);
        if (lane < 30 && i < D) f = s_fw4[i];
#pragma unroll
        for (int o = 16; o >= 1; o >>= 1) {
            f.x += __shfl_down_sync(0xffffffffu, f.x, o);
            f.y += __shfl_down_sync(0xffffffffu, f.y, o);
            f.z += __shfl_down_sync(0xffffffffu, f.z, o);
            f.w += __shfl_down_sync(0xffffffffu, f.w, o);
        }
        if (lane == 0) s_chunk[w] = f;
    }
    __syncthreads();

    float P0 = 0.f, P1 = 0.f, P2 = 0.f, P3 = 0.f;
    int widx = (w + b) & 15;          // rotate lists across CTAs for balance

#pragma unroll 1
    for (int bi = 0; bi < 2; ++bi) {
        int4 BL = c_blk[widx][bi];
        int jbase = BL.x;
        if (jbase < 0) break;
        int o0 = BL.y, o1 = BL.z, addc = BL.w;

        int j = jbase - 1 + lane;
        bool jv = (j >= 0) && (j < D);
        int  jm     = jv ? j : 0x7fffffff;
        float  cs_j = jv ? s_cs[j] : 0.f;
        float4 fwj  = jv ? s_fw4[j] : make_float4(0.f, 0.f, 0.f, 0.f);
        bool outv = (lane >= 1) && (lane <= 30) && (j < D);
        const float4* tb = s_tab4 + (jv ? 0 : 55);   // zero table for halo-invalid

        int it_hi = min(o1 + 1, D - 1);
        int it    = max(max(jbase - 1, o0 - 1), 0);
        int r_end = min(jbase + 30, o1 + 2);
        int warm_end = max(r_end, it + 2);
        warm_end += (warm_end & 1);                  // even start for float2 rs

        float r0l0 = 0.f, r0l1 = 0.f, r0l2 = 0.f;
        float r1l0 = 0.f, r1l1 = 0.f, r1l2 = 0.f;
        float r2l0 = 0.f, r2l1 = 0.f, r2l2 = 0.f;
        float r3l0 = 0.f, r3l1 = 0.f, r3l2 = 0.f;
        float ysum = 0.f;

        // ---- phase 1: masked scalar ramp ----
        for (; it < warm_end; ++it) {
            float e = s_rs[it] + cs_j;
            int idx = 0;
#pragma unroll
            for (int m = 0; m < NBP; ++m) { if (e > bp[m]) ++idx; }
            if ((it >= jm) && (it <= it_hi)) {
                const float4* tp = s_tab4 + idx * 5;
                float4 q0 = tp[0], q1 = tp[1], q2 = tp[2], q3 = tp[3], q4 = tp[4];
                r2l0 += fmaf(q0.x, e, q0.y);
                r2l1 += fmaf(q0.z, e, q0.w);
                r2l2 += fmaf(q1.x, e, q1.y);
                r1l0 += fmaf(q1.z, e, q1.w);
                r1l1 += fmaf(q2.x, e, q2.y);
                r1l2 += fmaf(q2.z, e, q2.w);
                r0l0 += fmaf(q3.x, e, q3.y);
                r0l1 += fmaf(q3.z, e, q3.w);
                r0l2 += fmaf(q4.x, e, q4.y);
            }
            int i = it - 1;
            float left  = __shfl_up_sync(0xffffffffu, r0l0, 1);
            float right = __shfl_down_sync(0xffffffffu, r0l2, 1);
            if (i >= o0 && i <= o1 && outv) {
                float y = fmaxf(left + r0l1 + right + b2v, 0.f);
                float4 fwi = s_fw4[i];
                ysum += y;
                P0 = fmaf(y, fwi.x, P0);
                P1 = fmaf(y, fwi.y, P1);
                P2 = fmaf(y, fwi.z, P2);
                P3 = fmaf(y, fwi.w, P3);
            }
            r0l0 = r1l0; r0l1 = r1l1; r0l2 = r1l2;
            r1l0 = r2l0; r1l1 = r2l1; r1l2 = r2l2;
            r2l0 = 0.f;  r2l1 = 0.f;  r2l2 = 0.f;
        }

        // ---- phase 2: unconditional 2-row steady pipeline ----
#pragma unroll 2
        for (; it + 1 <= it_hi; it += 2) {
            float2 rs2 = *reinterpret_cast<const float2*>(&s_rs[it]);
            float ea = rs2.x + cs_j;
            float eb = rs2.y + cs_j;
            int ia = 0, ib = 0;
#pragma unroll
            for (int m = 0; m < NBP; ++m) {
                if (ea > bp[m]) ++ia;
                if (eb > bp[m]) ++ib;
            }
            const float4* ta  = tb + ia * 5;
            const float4* tbb = tb + ib * 5;
            {
                float4 q0 = ta[0], q1 = ta[1], q2 = ta[2], q3 = ta[3], q4 = ta[4];
                r2l0 += fmaf(q0.x, ea, q0.y);
                r2l1 += fmaf(q0.z, ea, q0.w);
                r2l2 += fmaf(q1.x, ea, q1.y);
                r1l0 += fmaf(q1.z, ea, q1.w);
                r1l1 += fmaf(q2.x, ea, q2.y);
                r1l2 += fmaf(q2.z, ea, q2.w);
                r0l0 += fmaf(q3.x, ea, q3.y);
                r0l1 += fmaf(q3.z, ea, q3.w);
                r0l2 += fmaf(q4.x, ea, q4.y);
            }
            {
                float4 q0 = tbb[0], q1 = tbb[1], q2 = tbb[2], q3 = tbb[3], q4 = tbb[4];
                r3l0 += fmaf(q0.x, eb, q0.y);
                r3l1 += fmaf(q0.z, eb, q0.w);
                r3l2 += fmaf(q1.x, eb, q1.y);
                r2l0 += fmaf(q1.z, eb, q1.w);
                r2l1 += fmaf(q2.x, eb, q2.y);
                r2l2 += fmaf(q2.z, eb, q2.w);
                r1l0 += fmaf(q3.x, eb, q3.y);
                r1l1 += fmaf(q3.z, eb, q3.w);
                r1l2 += fmaf(q4.x, eb, q4.y);
            }
            float left0  = __shfl_up_sync(0xffffffffu, r0l0, 1);
            float right0 = __shfl_down_sync(0xffffffffu, r0l2, 1);
            float left1  = __shfl_up_sync(0xffffffffu, r1l0, 1);
            float right1 = __shfl_down_sync(0xffffffffu, r1l2, 1);
            float y0 = fmaxf(left0 + r0l1 + right0 + b2v, 0.f);
            float y1 = fmaxf(left1 + r1l1 + right1 + b2v, 0.f);
            if (outv) {
                float4 fwi0 = s_fw4[it - 1];
                float4 fwi1 = s_fw4[it];
                ysum += y0 + y1;
                P0 = fmaf(y0, fwi0.x, P0);
                P1 = fmaf(y0, fwi0.y, P1);
                P2 = fmaf(y0, fwi0.z, P2);
                P3 = fmaf(y0, fwi0.w, P3);
                P0 = fmaf(y1, fwi1.x, P0);
                P1 = fmaf(y1, fwi1.y, P1);
                P2 = fmaf(y1, fwi1.z, P2);
                P3 = fmaf(y1, fwi1.w, P3);
            }
            r0l0 = r2l0; r0l1 = r2l1; r0l2 = r2l2;
            r1l0 = r3l0; r1l1 = r3l1; r1l2 = r3l2;
            r2l0 = 0.f;  r2l1 = 0.f;  r2l2 = 0.f;
            r3l0 = 0.f;  r3l1 = 0.f;  r3l2 = 0.f;
        }

        // ---- phase 3: scalar tail ----
        for (; it <= o1 + 1; ++it) {
            float e = s_rs[it] + cs_j;
            int idx = 0;
#pragma unroll
            for (int m = 0; m < NBP; ++m) { if (e > bp[m]) ++idx; }
            if ((it >= jm) && (it <= it_hi)) {
                const float4* tp = s_tab4 + idx * 5;
                float4 q0 = tp[0], q1 = tp[1], q2 = tp[2], q3 = tp[3], q4 = tp[4];
                r2l0 += fmaf(q0.x, e, q0.y);
                r2l1 += fmaf(q0.z, e, q0.w);
                r2l2 += fmaf(q1.x, e, q1.y);
                r1l0 += fmaf(q1.z, e, q1.w);
                r1l1 += fmaf(q2.x, e, q2.y);
                r1l2 += fmaf(q2.z, e, q2.w);
                r0l0 += fmaf(q3.x, e, q3.y);
                r0l1 += fmaf(q3.z, e, q3.w);
                r0l2 += fmaf(q4.x, e, q4.y);
            }
            int i = it - 1;
            float left  = __shfl_up_sync(0xffffffffu, r0l0, 1);
            float right = __shfl_down_sync(0xffffffffu, r0l2, 1);
            if (i >= o0 && i <= o1 && outv) {
                float y = fmaxf(left + r0l1 + right + b2v, 0.f);
                float4 fwi = s_fw4[i];
                ysum += y;
                P0 = fmaf(y, fwi.x, P0);
                P1 = fmaf(y, fwi.y, P1);
                P2 = fmaf(y, fwi.z, P2);
                P3 = fmaf(y, fwi.w, P3);
            }
            r0l0 = r1l0; r0l1 = r1l1; r0l2 = r1l2;
            r1l0 = r2l0; r1l1 = r2l1; r1l2 = r2l2;
            r2l0 = 0.f;  r2l1 = 0.f;  r2l2 = 0.f;
        }

        // analytic constant region: rows 0..jbase-3 have y = relu(b2)
        if (addc && outv) {
            int sidx = jbase / 30;
            float4 pref = make_float4(0.f, 0.f, 0.f, 0.f);
            for (int c = 0; c < sidx; ++c) {
                float4 t = s_chunk[c];
                pref.x += t.x; pref.y += t.y; pref.z += t.z; pref.w += t.w;
            }
            float4 f1 = s_fw4[jbase - 1];
            float4 f2 = s_fw4[jbase - 2];
            pref.x -= f1.x + f2.x; pref.y -= f1.y + f2.y;
            pref.z -= f1.z + f2.z; pref.w -= f1.w + f2.w;
            P0 += cst * pref.x;
            P1 += cst * pref.y;
            P2 += cst * pref.z;
            P3 += cst * pref.w;
            ysum += cst * (float)(jbase - 2);
        }

        // fold column-weight part: P += ysum * fwj (fwj fixed per block)
        if (outv) {
            P0 = fmaf(ysum, fwj.x, P0);
            P1 = fmaf(ysum, fwj.y, P1);
            P2 = fmaf(ysum, fwj.z, P2);
            P3 = fmaf(ysum, fwj.w, P3);
        }
    }

#pragma unroll
    for (int o = 16; o >= 1; o >>= 1) {
        P0 += __shfl_down_sync(0xffffffffu, P0, o);
        P1 += __shfl_down_sync(0xffffffffu, P1, o);
        P2 += __shfl_down_sync(0xffffffffu, P2, o);
        P3 += __shfl_down_sync(0xffffffffu, P3, o);
    }
    if (lane == 0) s_red[w] = make_float4(P0, P1, P2, P3);
    __syncthreads();
    if (tid == 0) {
        float4 a = s_red[0];
#pragma unroll
        for (int k = 1; k < 16; ++k) {
            a.x += s_red[k].x; a.y += s_red[k].y;
            a.z += s_red[k].z; a.w += s_red[k].w;
        }
        g_part4[b] = a;
    }
}

// ------------------------------------------------------------------
__global__ void __launch_bounds__(512) final_kernel(const float* __restrict__ fc1_b,
                                                    const float* __restrict__ fc2_w,
                                                    const float* __restrict__ fc2_b,
                                                    float* __restrict__ out) {
    int t = threadIdx.x, lane = t & 31, w = t >> 5;
    __shared__ float4 s[16];
    float4 p = g_part4[t];
#pragma unroll
    for (int o = 16; o >= 1; o >>= 1) {
        p.x += __shfl_down_sync(0xffffffffu, p.x, o);
        p.y += __shfl_down_sync(0xffffffffu, p.y, o);
        p.z += __shfl_down_sync(0xffffffffu, p.z, o);
        p.w += __shfl_down_sync(0xffffffffu, p.w, o);
    }
    if (lane == 0) s[w] = p;
    __syncthreads();
    if (t == 0) {
        float4 a = s[0];
#pragma unroll
        for (int k = 1; k < 16; ++k) {
            a.x += s[k].x; a.y += s[k].y; a.z += s[k].z; a.w += s[k].w;
        }
        float h0 = fmaxf(a.x + fc1_b[0], 0.f);
        float h1 = fmaxf(a.y + fc1_b[1], 0.f);
        float h2 = fmaxf(a.z + fc1_b[2], 0.f);
        float h3 = fmaxf(a.w + fc1_b[3], 0.f);
        out[0] = fc2_b[0] + fc2_w[0] * h0 + fc2_w[1] * h1 + fc2_w[2] * h2 + fc2_w[3] * h3;
        out[1] = fc2_b[1] + fc2_w[4] * h0 + fc2_w[5] * h1 + fc2_w[6] * h2 + fc2_w[7] * h3;
    }
}

// ------------------------------------------------------------------
extern "C" void kernel_launch(void* const* d_in, const int* in_sizes, int n_in,
                              void* d_out, int out_size) {
    const float* x     = (const float*)d_in[0];
    const float* w1    = (const float*)d_in[1];
    const float* b1    = (const float*)d_in[2];
    const float* w2    = (const float*)d_in[3];
    const float* b2    = (const float*)d_in[4];
    const float* fc1_w = (const float*)d_in[5];
    const float* fc1_b = (const float*)d_in[6];
    const float* fc2_w = (const float*)d_in[7];
    const float* fc2_b = (const float*)d_in[8];
    float* out = (float*)d_out;

    // conv_kernel kept at launch index 3 so ncu (-s 5) profiles it
    setup_kernel<<<1, 128>>>(w1, b1, w2, b2);
    rowcol_kernel<<<BATCH, 256>>>(x);
    pad_kernel<<<1, 32>>>();
    conv_kernel<<<BATCH, 512>>>(fc1_w);
    final_kernel<<<1, 512>>>(fc1_b, fc2_w, fc2_b, out);
}